// round 12
// baseline (speedup 1.0000x reference)
#include <cuda_runtime.h>
#include <cuda_bf16.h>
#include <cstdint>

#define D_MODEL 1024
#define NTOK    4096
#define DFF_    4096
#define SEQ     2048
#define NH      16

// ---------------- scratch (device globals: allocation-free) ----------------
__device__ uint8_t       g_xn8    [(size_t)NTOK * D_MODEL];          // fp8 e4m3
__device__ uint8_t       g_attn8  [(size_t)NTOK * D_MODEL];          // fp8
__device__ uint8_t       g_ffin8  [(size_t)NTOK * DFF_];             // fp8
__device__ uint8_t       g_q8     [(size_t)NTOK * D_MODEL];          // fp8 x4
__device__ uint8_t       g_k8     [(size_t)NTOK * D_MODEL];          // fp8 x4
__device__ __nv_bfloat16 g_v_bf   [(size_t)NTOK * D_MODEL];
__device__ float         g_x1     [(size_t)NTOK * D_MODEL];
__device__ uint8_t       g_weqkv  [(size_t)3 * D_MODEL * D_MODEL];   // fp8 x64
__device__ uint8_t       g_weo    [(size_t)D_MODEL * D_MODEL];
__device__ uint8_t       g_we1    [(size_t)2 * DFF_ * D_MODEL];
__device__ uint8_t       g_we2    [(size_t)D_MODEL * DFF_];
__device__ __nv_bfloat16 g_abf    [(size_t)7168 * 32];               // A mats bf16
__device__ __nv_bfloat16 g_bt     [(size_t)13312 * 32];              // B^T mats bf16

#define WSCALE 64.0f
#define DEQ    (1.0f / 64.0f)
#define QS     4.0f
#define LOG2E  1.44269504f
#define ATTN_SCL2 (0.125f / 16.0f * LOG2E)

// ---------------- PTX helpers ----------------------------------------------
__device__ __forceinline__ void cp16(uint32_t s, const void* g) {
    asm volatile("cp.async.cg.shared.global [%0], [%1], 16;\n" :: "r"(s), "l"(g));
}
__device__ __forceinline__ void ldmx4(uint32_t* r, uint32_t addr) {
    asm volatile("ldmatrix.sync.aligned.m8n8.x4.shared.b16 {%0,%1,%2,%3}, [%4];"
                 : "=r"(r[0]), "=r"(r[1]), "=r"(r[2]), "=r"(r[3]) : "r"(addr));
}
__device__ __forceinline__ void ldmx4t(uint32_t* r, uint32_t addr) {
    asm volatile("ldmatrix.sync.aligned.m8n8.x4.trans.shared.b16 {%0,%1,%2,%3}, [%4];"
                 : "=r"(r[0]), "=r"(r[1]), "=r"(r[2]), "=r"(r[3]) : "r"(addr));
}
#define MMA_BF16(d, a, b0, b1) \
    asm volatile("mma.sync.aligned.m16n8k16.row.col.f32.bf16.bf16.f32 " \
                 "{%0,%1,%2,%3}, {%4,%5,%6,%7}, {%8,%9}, {%0,%1,%2,%3};" \
                 : "+f"(d[0]), "+f"(d[1]), "+f"(d[2]), "+f"(d[3]) \
                 : "r"(a[0]), "r"(a[1]), "r"(a[2]), "r"(a[3]), "r"(b0), "r"(b1))
#define MMA_FP8(d, a, b0, b1) \
    asm volatile("mma.sync.aligned.m16n8k32.row.col.f32.e4m3.e4m3.f32 " \
                 "{%0,%1,%2,%3}, {%4,%5,%6,%7}, {%8,%9}, {%0,%1,%2,%3};" \
                 : "+f"(d[0]), "+f"(d[1]), "+f"(d[2]), "+f"(d[3]) \
                 : "r"(a[0]), "r"(a[1]), "r"(a[2]), "r"(a[3]), "r"(b0), "r"(b1))
#define CPCOMMIT() asm volatile("cp.async.commit_group;\n" ::)

__device__ __forceinline__ uint32_t packbf(float a, float b) {
    __nv_bfloat162 t = __floats2bfloat162_rn(a, b);
    return *(uint32_t*)&t;
}
__device__ __forceinline__ uint16_t packf8(float a, float b) {
    uint16_t r;
    asm("cvt.rn.satfinite.e4m3x2.f32 %0, %1, %2;" : "=h"(r) : "f"(b), "f"(a));
    return r;
}
__device__ __forceinline__ uint8_t f2f8(float v) {
    uint16_t r;
    asm("cvt.rn.satfinite.e4m3x2.f32 %0, %1, %2;" : "=h"(r) : "f"(0.f), "f"(v));
    return (uint8_t)(r & 0xFF);
}
__device__ __forceinline__ float ex2(float x) {
    float y;
    asm("ex2.approx.ftz.f32 %0, %1;" : "=f"(y) : "f"(x));
    return y;
}

// ---------------- prep: A -> bf16, B -> B^T bf16 ---------------------------
// abf concat rows: [Aq 1024 | Ao 1024 | A1 1024 | A2 4096] x 32
// bt  concat rows: [Bq^T 3072 | Bo^T 1024 | B1^T 8192 | B2^T 1024] x 32
__global__ void __launch_bounds__(256) prep_kernel(
        __nv_bfloat16* __restrict__ abf, __nv_bfloat16* __restrict__ bt,
        const float* __restrict__ Aq, const float* __restrict__ Ao_,
        const float* __restrict__ A1_, const float* __restrict__ A2_,
        const float* __restrict__ Bq, const float* __restrict__ Bo_,
        const float* __restrict__ B1_, const float* __restrict__ B2_) {
    if (blockIdx.x < 448) {   // A convert: 229376 elems as float2
        const size_t idx = ((size_t)blockIdx.x * 256 + threadIdx.x) * 2;
        float2 v;
        if (idx < 32768)       v = *(const float2*)(Aq  + idx);
        else if (idx < 65536)  v = *(const float2*)(Ao_ + idx - 32768);
        else if (idx < 98304)  v = *(const float2*)(A1_ + idx - 65536);
        else                   v = *(const float2*)(A2_ + idx - 98304);
        *(uint32_t*)(abf + idx) = packbf(v.x, v.y);
    } else {                  // B transpose: 425984 elems
        const int i = (blockIdx.x - 448) * 256 + threadIdx.x;
        const int j = i >> 5, r = i & 31;
        float v;
        if (j < 3072)       v = Bq [(size_t)r * 3072 + j];
        else if (j < 4096)  v = Bo_[(size_t)r * 1024 + (j - 3072)];
        else if (j < 12288) v = B1_[(size_t)r * 8192 + (j - 4096)];
        else                v = B2_[(size_t)r * 1024 + (j - 12288)];
        bt[i] = __float2bfloat16_rn(v);
    }
}

// ---------------- weff via bf16 tensor-core K=32 GEMM ----------------------
// out[remap(j)][d] = e4m3( (W[j][d] + (BtA^T)[j][d]/32) * 64 )
// Tile 128j x 128d; grid 1024 linear with 4-way dispatch.
__global__ void __launch_bounds__(256, 2) weff_gemm(
        const __nv_bfloat16* __restrict__ abf, const __nv_bfloat16* __restrict__ bt,
        const float* __restrict__ Wq, const float* __restrict__ Wo_,
        const float* __restrict__ W1_, const float* __restrict__ W2_,
        uint8_t* __restrict__ o0, uint8_t* __restrict__ o1,
        uint8_t* __restrict__ o2, uint8_t* __restrict__ o3) {
    __shared__ __align__(16) char sm[2 * 10240];
    const uint32_t sX = (uint32_t)__cvta_generic_to_shared(sm);
    const uint32_t sY = sX + 10240;
    const int tid = threadIdx.x, lane = tid & 31, warp = tid >> 5;
    const int wm = warp >> 1, wn = warp & 1;
    const int bid = blockIdx.x;
    int which, tloc;
    if (bid < 192)      { which = 0; tloc = bid; }
    else if (bid < 256) { which = 1; tloc = bid - 192; }
    else if (bid < 768) { which = 2; tloc = bid - 256; }
    else                { which = 3; tloc = bid - 768; }
    const int KT = (which == 3) ? 32 : 8;
    const int Km = (which == 3) ? 4096 : 1024;
    const int bx = tloc % KT, by = tloc / KT;
    const int jb = (which == 0) ? 0 : (which == 1) ? 3072 : (which == 2) ? 4096 : 12288;
    const int db = which * 1024;   // {0,1024,2048,3072}
    const float* W = (which == 0) ? Wq : (which == 1) ? Wo_ : (which == 2) ? W1_ : W2_;
    uint8_t* out   = (which == 0) ? o0 : (which == 1) ? o1 : (which == 2) ? o2 : o3;

    #pragma unroll
    for (int i = 0; i < 2; ++i) {
        const int c = tid + i * 256;
        const int row = c >> 2, ch = c & 3;
        cp16(sX + row * 80 + ch * 16, bt  + ((size_t)(jb + by * 128 + row)) * 32 + ch * 8);
        cp16(sY + row * 80 + ch * 16, abf + ((size_t)(db + bx * 128 + row)) * 32 + ch * 8);
    }
    CPCOMMIT();
    asm volatile("cp.async.wait_group 0;" ::: "memory");
    __syncthreads();

    float acc[2][8][4];
    #pragma unroll
    for (int mi = 0; mi < 2; ++mi)
        #pragma unroll
        for (int ni = 0; ni < 8; ++ni)
            #pragma unroll
            for (int e = 0; e < 4; ++e) acc[mi][ni][e] = 0.f;

    const int lr = lane & 15, lh = lane >> 4;
    #pragma unroll
    for (int ks = 0; ks < 2; ++ks) {
        uint32_t a[2][4], b[4][4];
        #pragma unroll
        for (int mi = 0; mi < 2; ++mi)
            ldmx4(a[mi], sX + (wm * 32 + mi * 16 + lr) * 80 + ks * 32 + lh * 16);
        #pragma unroll
        for (int nj = 0; nj < 4; ++nj)
            ldmx4(b[nj], sY + (wn * 64 + nj * 16 + lr) * 80 + ks * 32 + lh * 16);
        #pragma unroll
        for (int mi = 0; mi < 2; ++mi)
            #pragma unroll
            for (int ni = 0; ni < 8; ++ni)
                MMA_BF16(acc[mi][ni], a[mi], b[ni >> 1][ni & 1], b[ni >> 1][(ni & 1) + 2]);
    }

    const int g = lane >> 2, tg = lane & 3;
    #pragma unroll
    for (int mi = 0; mi < 2; ++mi) {
        #pragma unroll
        for (int ni = 0; ni < 8; ++ni) {
            const int col = bx * 128 + wn * 64 + ni * 8 + tg * 2;
            #pragma unroll
            for (int half = 0; half < 2; ++half) {
                const int j = by * 128 + wm * 32 + mi * 16 + g + half * 8;
                const int jout = (which == 2)
                    ? ((j < DFF_) ? 2 * j : 2 * (j - DFF_) + 1) : j;
                const float2 wv = *(const float2*)(W + (size_t)j * Km + col);
                const float v0 = (wv.x + acc[mi][ni][2 * half]     * (1.f / 32.f)) * WSCALE;
                const float v1 = (wv.y + acc[mi][ni][2 * half + 1] * (1.f / 32.f)) * WSCALE;
                *(uint16_t*)(out + (size_t)jout * Km + col) = packf8(v0, v1);
            }
        }
    }
}

// ---------------- LayerNorm (one block per row, D=1024), fp8 out -----------
__global__ void __launch_bounds__(256) ln_kernel(const float* __restrict__ xin,
        const float* __restrict__ gw, const float* __restrict__ bw,
        uint8_t* __restrict__ y) {
    __shared__ float sred[64];
    const int row = blockIdx.x, tid = threadIdx.x;
    const float4 v = ((const float4*)(xin + (size_t)row * 1024))[tid];
    float s = v.x + v.y + v.z + v.w;
    float q = v.x * v.x + v.y * v.y + v.z * v.z + v.w * v.w;
    #pragma unroll
    for (int off = 16; off; off >>= 1) {
        s += __shfl_xor_sync(0xffffffffu, s, off);
        q += __shfl_xor_sync(0xffffffffu, q, off);
    }
    if ((tid & 31) == 0) { sred[tid >> 5] = s; sred[32 + (tid >> 5)] = q; }
    __syncthreads();
    s = 0.f; q = 0.f;
    #pragma unroll
    for (int i = 0; i < 8; ++i) { s += sred[i]; q += sred[32 + i]; }
    const float mu   = s * (1.f / 1024.f);
    const float var  = q * (1.f / 1024.f) - mu * mu;
    const float rstd = rsqrtf(var + 1e-6f);
    const float4 g4 = ((const float4*)gw)[tid];
    const float4 b4 = ((const float4*)bw)[tid];
    const float y0 = (v.x - mu) * rstd * g4.x + b4.x;
    const float y1 = (v.y - mu) * rstd * g4.y + b4.y;
    const float y2 = (v.z - mu) * rstd * g4.z + b4.z;
    const float y3 = (v.w - mu) * rstd * g4.w + b4.w;
    *(uint32_t*)(y + (size_t)row * 1024 + tid * 4) =
        (uint32_t)packf8(y0, y1) | ((uint32_t)packf8(y2, y3) << 16);
}

// ---------------- fp8 mma GEMM: C[M,N] = (A[M,K] * B[N,K]^T) * DEQ ---------
#define GSTG 4
#define GSTAGE_BYTES 20480

template <int EPI>
__global__ void __launch_bounds__(256, 2) gemm_fp8_nt(
        const uint8_t* __restrict__ A, const uint8_t* __restrict__ B,
        void* __restrict__ Cout, const void* __restrict__ aux1,
        const void* __restrict__ aux2, int M, int N, int K) {
    extern __shared__ char smem[];
    const uint32_t sbase = (uint32_t)__cvta_generic_to_shared(smem);
    const int tid = threadIdx.x, lane = tid & 31, warp = tid >> 5;
    const int wm = warp >> 1, wn = warp & 1;
    const int bm = blockIdx.y, bn = blockIdx.x;
    const uint8_t* Ab = A + (size_t)bm * 128 * K;
    const uint8_t* Bb = B + (size_t)bn * 128 * K;
    const int NKT = K >> 6;

    const int r0 = tid >> 2, fof = (tid & 3) * 16;
    const int r1 = r0 + 64;

    auto issue = [&](int st, int kt) {
        const uint32_t sA = sbase + st * GSTAGE_BYTES;
        const uint32_t sB = sA + 10240;
        const int kof = kt * 64;
        cp16(sA + r0 * 80 + fof, Ab + (size_t)r0 * K + kof + fof);
        cp16(sA + r1 * 80 + fof, Ab + (size_t)r1 * K + kof + fof);
        cp16(sB + r0 * 80 + fof, Bb + (size_t)r0 * K + kof + fof);
        cp16(sB + r1 * 80 + fof, Bb + (size_t)r1 * K + kof + fof);
        CPCOMMIT();
    };

    #pragma unroll
    for (int s = 0; s < GSTG - 1; ++s) issue(s, s);

    float acc[2][8][4];
    #pragma unroll
    for (int mi = 0; mi < 2; ++mi)
        #pragma unroll
        for (int ni = 0; ni < 8; ++ni)
            #pragma unroll
            for (int e = 0; e < 4; ++e) acc[mi][ni][e] = 0.f;

    const int lr = lane & 15, lh = lane >> 4;

    for (int kt = 0; kt < NKT; ++kt) {
        asm volatile("cp.async.wait_group %0;\n" :: "n"(GSTG - 2));
        __syncthreads();
        if (kt + GSTG - 1 < NKT) issue((kt + GSTG - 1) & (GSTG - 1), kt + GSTG - 1);
        else CPCOMMIT();

        const uint32_t sA = sbase + (kt & (GSTG - 1)) * GSTAGE_BYTES;
        const uint32_t sB = sA + 10240;
        #pragma unroll
        for (int ks = 0; ks < 2; ++ks) {
            uint32_t a[2][4], b[4][4];
            #pragma unroll
            for (int mi = 0; mi < 2; ++mi)
                ldmx4(a[mi], sA + (wm * 32 + mi * 16 + lr) * 80 + ks * 32 + lh * 16);
            #pragma unroll
            for (int nj = 0; nj < 4; ++nj)
                ldmx4(b[nj], sB + (wn * 64 + nj * 16 + lr) * 80 + ks * 32 + lh * 16);
            #pragma unroll
            for (int mi = 0; mi < 2; ++mi)
                #pragma unroll
                for (int ni = 0; ni < 8; ++ni)
                    MMA_FP8(acc[mi][ni], a[mi], b[ni >> 1][ni & 1], b[ni >> 1][(ni & 1) + 2]);
        }
    }

    const int g = lane >> 2, tg = lane & 3;
    #pragma unroll
    for (int mi = 0; mi < 2; ++mi) {
        const int row = bm * 128 + wm * 32 + mi * 16 + g;
        #pragma unroll
        for (int ni = 0; ni < 8; ++ni) {
            const int col = bn * 128 + wn * 64 + ni * 8 + tg * 2;
            if constexpr (EPI == 1) {
                uint8_t* C = (uint8_t*)Cout;
                const int oc = col >> 1;
                const int oN = N >> 1;
                const float gt0 = acc[mi][ni][0] * DEQ, at0 = acc[mi][ni][1] * DEQ;
                const float gt1 = acc[mi][ni][2] * DEQ, at1 = acc[mi][ni][3] * DEQ;
                C[(size_t)row * oN + oc]       = f2f8(gt0 / (1.f + __expf(-gt0)) * at0);
                C[(size_t)(row + 8) * oN + oc] = f2f8(gt1 / (1.f + __expf(-gt1)) * at1);
            } else if constexpr (EPI == 2) {
                float* C = (float*)Cout;
                const float* resid = (const float*)aux1;
                const float* ls    = (const float*)aux2;
                const float2 lv = *(const float2*)(ls + col);
                const float2 x0 = *(const float2*)(resid + (size_t)row * N + col);
                const float2 x1 = *(const float2*)(resid + (size_t)(row + 8) * N + col);
                *(float2*)(C + (size_t)row * N + col) =
                    make_float2(x0.x + lv.x * acc[mi][ni][0] * DEQ,
                                x0.y + lv.y * acc[mi][ni][1] * DEQ);
                *(float2*)(C + (size_t)(row + 8) * N + col) =
                    make_float2(x1.x + lv.x * acc[mi][ni][2] * DEQ,
                                x1.y + lv.y * acc[mi][ni][3] * DEQ);
            } else {  // EPI == 3: qkv split
                if (col < 2048) {
                    uint8_t* dst = (uint8_t*)(col < 1024 ? Cout : (void*)aux1);
                    const int c = col & 1023;
                    *(uint16_t*)(dst + (size_t)row * 1024 + c) =
                        packf8(acc[mi][ni][0] * (DEQ * QS), acc[mi][ni][1] * (DEQ * QS));
                    *(uint16_t*)(dst + (size_t)(row + 8) * 1024 + c) =
                        packf8(acc[mi][ni][2] * (DEQ * QS), acc[mi][ni][3] * (DEQ * QS));
                } else {
                    __nv_bfloat16* v = (__nv_bfloat16*)aux2;
                    const int c = col - 2048;
                    *(uint32_t*)(v + (size_t)row * 1024 + c) =
                        packbf(acc[mi][ni][0] * DEQ, acc[mi][ni][1] * DEQ);
                    *(uint32_t*)(v + (size_t)(row + 8) * 1024 + c) =
                        packbf(acc[mi][ni][2] * DEQ, acc[mi][ni][3] * DEQ);
                }
            }
        }
    }
}

// ---------------- flash attention: fp8 QK^T, bf16 P*V, log2 softmax --------
// 4-stage KV ring, single barrier per tile.
#define AKV_STAGE 14336
#define ATTN_SMEM (10240 + 4 * AKV_STAGE)

__global__ void __launch_bounds__(256, 2) attn_tc(
        const uint8_t* __restrict__ q8, const uint8_t* __restrict__ k8,
        const __nv_bfloat16* __restrict__ vbf, uint8_t* __restrict__ outp) {
    extern __shared__ char smraw[];
    const uint32_t sQ = (uint32_t)__cvta_generic_to_shared(smraw);
    const int qt = (int)(gridDim.x - 1 - blockIdx.x);
    const int h = blockIdx.y, b = blockIdx.z;
    const int tid = threadIdx.x, lane = tid & 31, w = tid >> 5;
    const int g = lane >> 2, tg = lane & 3;
    const int lr = lane & 15, lh = lane >> 4;
    const float slope2 = exp2f(-0.5f * (float)(h + 1)) * LOG2E;
    const size_t rowbase = (size_t)b * SEQ;

    #pragma unroll
    for (int i = 0; i < 2; ++i) {
        const int c = tid + i * 256;
        const int row = c >> 2, off = (c & 3) * 16;
        cp16(sQ + row * 80 + off,
             q8 + (rowbase + qt * 128 + row) * 1024 + h * 64 + off);
    }
    CPCOMMIT();

    const int ktmax = 2 * qt + 1;
    auto issueKV = [&](int kt) {
        const uint32_t sK = sQ + 10240 + (kt & 3) * AKV_STAGE;
        const uint32_t sV = sK + 5120;
        {
            const int row = tid >> 2, off = (tid & 3) * 16;
            cp16(sK + row * 80 + off,
                 k8 + (rowbase + kt * 64 + row) * 1024 + h * 64 + off);
        }
        #pragma unroll
        for (int i = 0; i < 2; ++i) {
            const int c = tid + i * 256;
            const int row = c >> 3, off = (c & 7) * 8;
            cp16(sV + row * 144 + off * 2,
                 vbf + (rowbase + kt * 64 + row) * 1024 + h * 64 + off);
        }
        CPCOMMIT();
    };
    issueKV(0);
    issueKV(1);
    if (ktmax >= 2) issueKV(2); else CPCOMMIT();

    asm volatile("cp.async.wait_group %0;\n" :: "n"(3));
    __syncthreads();
    uint32_t qa[2][4];
    #pragma unroll
    for (int ks = 0; ks < 2; ++ks)
        ldmx4(qa[ks], sQ + (w * 16 + lr) * 80 + ks * 32 + lh * 16);

    float o[8][4];
    #pragma unroll
    for (int ni = 0; ni < 8; ++ni)
        #pragma unroll
        for (int e = 0; e < 4; ++e) o[ni][e] = 0.f;
    float m0 = -1e30f, m1 = -1e30f, l0 = 0.f, l1 = 0.f;

    const int qr0 = qt * 128 + w * 16 + g;
    const int qwmin = qt * 128 + w * 16;
    const int qwmax = qwmin + 15;

    for (int kt = 0; kt <= ktmax; ++kt) {
        asm volatile("cp.async.wait_group %0;\n" :: "n"(2));
        __syncthreads();
        if (kt * 64 <= qwmax) {
            const uint32_t sK = sQ + 10240 + (kt & 3) * AKV_STAGE;
            const uint32_t sV = sK + 5120;
            float sc[8][4];
            #pragma unroll
            for (int ni = 0; ni < 8; ++ni)
                #pragma unroll
                for (int e = 0; e < 4; ++e) sc[ni][e] = 0.f;
            #pragma unroll
            for (int ks = 0; ks < 2; ++ks) {
                uint32_t kb[4][4];
                #pragma unroll
                for (int nj = 0; nj < 4; ++nj)
                    ldmx4(kb[nj], sK + (nj * 16 + lr) * 80 + ks * 32 + lh * 16);
                #pragma unroll
                for (int ni = 0; ni < 8; ++ni)
                    MMA_FP8(sc[ni], qa[ks], kb[ni >> 1][ni & 1], kb[ni >> 1][(ni & 1) + 2]);
            }
            #pragma unroll
            for (int ni = 0; ni < 8; ++ni) {
                const float kcf = (float)(kt * 64 + ni * 8 + tg * 2);
                const float b0 = slope2 * kcf;
                const float b1 = slope2 * (kcf + 1.f);
                sc[ni][0] = sc[ni][0] * ATTN_SCL2 + b0;
                sc[ni][1] = sc[ni][1] * ATTN_SCL2 + b1;
                sc[ni][2] = sc[ni][2] * ATTN_SCL2 + b0;
                sc[ni][3] = sc[ni][3] * ATTN_SCL2 + b1;
            }
            if ((kt * 64 + 63) > qwmin) {
                #pragma unroll
                for (int ni = 0; ni < 8; ++ni) {
                    const int kc = kt * 64 + ni * 8 + tg * 2;
                    #pragma unroll
                    for (int e = 0; e < 4; ++e) {
                        const int q = (e < 2) ? qr0 : qr0 + 8;
                        if (kc + (e & 1) > q) sc[ni][e] = -1e30f;
                    }
                }
            }
            float rm0 = -1e30f, rm1 = -1e30f;
            #pragma unroll
            for (int ni = 0; ni < 8; ++ni) {
                rm0 = fmaxf(rm0, fmaxf(sc[ni][0], sc[ni][1]));
                rm1 = fmaxf(rm1, fmaxf(sc[ni][2], sc[ni][3]));
            }
            rm0 = fmaxf(rm0, __shfl_xor_sync(0xffffffffu, rm0, 1));
            rm0 = fmaxf(rm0, __shfl_xor_sync(0xffffffffu, rm0, 2));
            rm1 = fmaxf(rm1, __shfl_xor_sync(0xffffffffu, rm1, 1));
            rm1 = fmaxf(rm1, __shfl_xor_sync(0xffffffffu, rm1, 2));
            const float mn0 = fmaxf(m0, rm0), mn1 = fmaxf(m1, rm1);
            const float cs0 = ex2(m0 - mn0), cs1 = ex2(m1 - mn1);
            float ps0 = 0.f, ps1 = 0.f;
            #pragma unroll
            for (int ni = 0; ni < 8; ++ni) {
                sc[ni][0] = ex2(sc[ni][0] - mn0); ps0 += sc[ni][0];
                sc[ni][1] = ex2(sc[ni][1] - mn0); ps0 += sc[ni][1];
                sc[ni][2] = ex2(sc[ni][2] - mn1); ps1 += sc[ni][2];
                sc[ni][3] = ex2(sc[ni][3] - mn1); ps1 += sc[ni][3];
            }
            ps0 += __shfl_xor_sync(0xffffffffu, ps0, 1);
            ps0 += __shfl_xor_sync(0xffffffffu, ps0, 2);
            ps1 += __shfl_xor_sync(0xffffffffu, ps1, 1);
            ps1 += __shfl_xor_sync(0xffffffffu, ps1, 2);
            l0 = l0 * cs0 + ps0; l1 = l1 * cs1 + ps1;
            m0 = mn0; m1 = mn1;
            #pragma unroll
            for (int ni = 0; ni < 8; ++ni) {
                o[ni][0] *= cs0; o[ni][1] *= cs0;
                o[ni][2] *= cs1; o[ni][3] *= cs1;
            }
            #pragma unroll
            for (int j = 0; j < 4; ++j) {
                uint32_t pa[4];
                pa[0] = packbf(sc[2 * j][0],     sc[2 * j][1]);
                pa[1] = packbf(sc[2 * j][2],     sc[2 * j][3]);
                pa[2] = packbf(sc[2 * j + 1][0], sc[2 * j + 1][1]);
                pa[3] = packbf(sc[2 * j + 1][2], sc[2 * j + 1][3]);
                #pragma unroll
                for (int nt = 0; nt < 4; ++nt) {
                    uint32_t vb[4];
                    ldmx4t(vb, sV + ((j * 16 + (lane & 7) + ((lane >> 3) & 1) * 8) * 144)
                                  + (nt * 16 + ((lane >> 4) & 1) * 8) * 2);
                    MMA_BF16(o[2 * nt],     pa, vb[0], vb[1]);
                    MMA_BF16(o[2 * nt + 1], pa, vb[2], vb[3]);
                }
            }
        }
        if (kt + 3 <= ktmax) issueKV(kt + 3);
        else CPCOMMIT();
    }

    const float inv0 = 1.f / l0, inv1 = 1.f / l1;
    const size_t row0 = rowbase + qr0;
    #pragma unroll
    for (int ni = 0; ni < 8; ++ni) {
        const int col = h * 64 + ni * 8 + tg * 2;
        *(uint16_t*)(outp + row0 * D_MODEL + col) =
            packf8(o[ni][0] * inv0, o[ni][1] * inv0);
        *(uint16_t*)(outp + (row0 + 8) * D_MODEL + col) =
            packf8(o[ni][2] * inv1, o[ni][3] * inv1);
    }
}

// ---------------- launch ---------------------------------------------------
extern "C" void kernel_launch(void* const* d_in, const int* in_sizes, int n_in,
                              void* d_out, int out_size) {
    (void)in_sizes; (void)n_in; (void)out_size;
    const float* x    = (const float*)d_in[0];
    const float* ln1g = (const float*)d_in[2];
    const float* ln1b = (const float*)d_in[3];
    const float* Wqkv = (const float*)d_in[4];
    const float* Aqkv = (const float*)d_in[5];
    const float* Bqkv = (const float*)d_in[6];
    const float* Wo   = (const float*)d_in[7];
    const float* Ao   = (const float*)d_in[8];
    const float* Bo   = (const float*)d_in[9];
    const float* ln2g = (const float*)d_in[10];
    const float* ln2b = (const float*)d_in[11];
    const float* W1   = (const float*)d_in[12];
    const float* A1   = (const float*)d_in[13];
    const float* B1   = (const float*)d_in[14];
    const float* W2   = (const float*)d_in[15];
    const float* A2   = (const float*)d_in[16];
    const float* B2   = (const float*)d_in[17];
    const float* ls1  = (const float*)d_in[18];
    const float* ls2  = (const float*)d_in[19];
    float* out = (float*)d_out;

    uint8_t *p_xn, *p_attn, *p_ffin, *p_q8, *p_k8;
    uint8_t *p_weqkv, *p_weo, *p_we1, *p_we2;
    __nv_bfloat16 *p_v, *p_abf, *p_bt;
    float *p_x1;
    cudaGetSymbolAddress((void**)&p_xn,    g_xn8);
    cudaGetSymbolAddress((void**)&p_attn,  g_attn8);
    cudaGetSymbolAddress((void**)&p_ffin,  g_ffin8);
    cudaGetSymbolAddress((void**)&p_q8,    g_q8);
    cudaGetSymbolAddress((void**)&p_k8,    g_k8);
    cudaGetSymbolAddress((void**)&p_v,     g_v_bf);
    cudaGetSymbolAddress((void**)&p_x1,    g_x1);
    cudaGetSymbolAddress((void**)&p_weqkv, g_weqkv);
    cudaGetSymbolAddress((void**)&p_weo,   g_weo);
    cudaGetSymbolAddress((void**)&p_we1,   g_we1);
    cudaGetSymbolAddress((void**)&p_we2,   g_we2);
    cudaGetSymbolAddress((void**)&p_abf,   g_abf);
    cudaGetSymbolAddress((void**)&p_bt,    g_bt);

    const int smem_gemm = GSTG * GSTAGE_BYTES;   // 81920
    cudaFuncSetAttribute((const void*)gemm_fp8_nt<1>, cudaFuncAttributeMaxDynamicSharedMemorySize, smem_gemm);
    cudaFuncSetAttribute((const void*)gemm_fp8_nt<2>, cudaFuncAttributeMaxDynamicSharedMemorySize, smem_gemm);
    cudaFuncSetAttribute((const void*)gemm_fp8_nt<3>, cudaFuncAttributeMaxDynamicSharedMemorySize, smem_gemm);
    cudaFuncSetAttribute((const void*)attn_tc,        cudaFuncAttributeMaxDynamicSharedMemorySize, ATTN_SMEM);

    // 1: prep (A->bf16, B->B^T bf16)
    prep_kernel<<<2112, 256>>>(p_abf, p_bt, Aqkv, Ao, A1, A2, Bqkv, Bo, B1, B2);
    // 2: LN1
    ln_kernel<<<NTOK, 256>>>(x, ln1g, ln1b, p_xn);
    // 3: weff via tensor-core GEMM (all four weights)
    weff_gemm<<<1024, 256>>>(p_abf, p_bt, Wqkv, Wo, W1, W2,
                             p_weqkv, p_weo, p_we1, p_we2);
    // 4: qkv GEMM (profiled slot)
    gemm_fp8_nt<3><<<dim3(3072 / 128, NTOK / 128), 256, smem_gemm>>>(
        p_xn, p_weqkv, p_q8, p_k8, p_v, NTOK, 3072, 1024);
    // 5: attention
    attn_tc<<<dim3(SEQ / 128, NH, 2), 256, ATTN_SMEM>>>(p_q8, p_k8, p_v, p_attn);
    // 6: o-proj + residual
    gemm_fp8_nt<2><<<dim3(1024 / 128, NTOK / 128), 256, smem_gemm>>>(
        p_attn, p_weo, p_x1, x, ls1, NTOK, 1024, 1024);
    // 7: LN2
    ln_kernel<<<NTOK, 256>>>(p_x1, ln2g, ln2b, p_xn);
    // 8: W1 + swiglu
    gemm_fp8_nt<1><<<dim3(8192 / 128, NTOK / 128), 256, smem_gemm>>>(
        p_xn, p_we1, p_ffin, nullptr, nullptr, NTOK, 8192, 1024);
    // 9: W2 + residual -> out
    gemm_fp8_nt<2><<<dim3(1024 / 128, NTOK / 128), 256, smem_gemm>>>(
        p_ffin, p_we2, out, p_x1, ls2, NTOK, 1024, 4096);
}

// round 14
// speedup vs baseline: 1.0095x; 1.0095x over previous
#include <cuda_runtime.h>
#include <cuda_bf16.h>
#include <cstdint>

#define D_MODEL 1024
#define NTOK    4096
#define DFF_    4096
#define SEQ     2048
#define NH      16

// ---------------- scratch (device globals: allocation-free) ----------------
__device__ uint8_t       g_xn8    [(size_t)NTOK * D_MODEL];          // fp8 e4m3
__device__ uint8_t       g_attn8  [(size_t)NTOK * D_MODEL];          // fp8
__device__ uint8_t       g_ffin8  [(size_t)NTOK * DFF_];             // fp8
__device__ uint8_t       g_q8     [(size_t)NTOK * D_MODEL];          // fp8 x4
__device__ uint8_t       g_k8     [(size_t)NTOK * D_MODEL];          // fp8 x4
__device__ __nv_bfloat16 g_v_bf   [(size_t)NTOK * D_MODEL];
__device__ float         g_x1     [(size_t)NTOK * D_MODEL];
__device__ uint8_t       g_weqkv  [(size_t)3 * D_MODEL * D_MODEL];   // fp8 x64
__device__ uint8_t       g_weo    [(size_t)D_MODEL * D_MODEL];
__device__ uint8_t       g_we1    [(size_t)2 * DFF_ * D_MODEL];
__device__ uint8_t       g_we2    [(size_t)D_MODEL * DFF_];
__device__ __nv_bfloat16 g_abf    [(size_t)7168 * 32];               // A mats bf16
__device__ __nv_bfloat16 g_bt     [(size_t)13312 * 32];              // B^T mats bf16

#define WSCALE 64.0f
#define DEQ    (1.0f / 64.0f)
#define QS     4.0f
#define LOG2E  1.44269504f
#define ATTN_SCL2 (0.125f / 16.0f * LOG2E)

// ---------------- PTX helpers ----------------------------------------------
__device__ __forceinline__ void cp16(uint32_t s, const void* g) {
    asm volatile("cp.async.cg.shared.global [%0], [%1], 16;\n" :: "r"(s), "l"(g));
}
__device__ __forceinline__ void ldmx4(uint32_t* r, uint32_t addr) {
    asm volatile("ldmatrix.sync.aligned.m8n8.x4.shared.b16 {%0,%1,%2,%3}, [%4];"
                 : "=r"(r[0]), "=r"(r[1]), "=r"(r[2]), "=r"(r[3]) : "r"(addr));
}
__device__ __forceinline__ void ldmx4t(uint32_t* r, uint32_t addr) {
    asm volatile("ldmatrix.sync.aligned.m8n8.x4.trans.shared.b16 {%0,%1,%2,%3}, [%4];"
                 : "=r"(r[0]), "=r"(r[1]), "=r"(r[2]), "=r"(r[3]) : "r"(addr));
}
#define MMA_BF16(d, a, b0, b1) \
    asm volatile("mma.sync.aligned.m16n8k16.row.col.f32.bf16.bf16.f32 " \
                 "{%0,%1,%2,%3}, {%4,%5,%6,%7}, {%8,%9}, {%0,%1,%2,%3};" \
                 : "+f"(d[0]), "+f"(d[1]), "+f"(d[2]), "+f"(d[3]) \
                 : "r"(a[0]), "r"(a[1]), "r"(a[2]), "r"(a[3]), "r"(b0), "r"(b1))
#define MMA_FP8(d, a, b0, b1) \
    asm volatile("mma.sync.aligned.m16n8k32.row.col.f32.e4m3.e4m3.f32 " \
                 "{%0,%1,%2,%3}, {%4,%5,%6,%7}, {%8,%9}, {%0,%1,%2,%3};" \
                 : "+f"(d[0]), "+f"(d[1]), "+f"(d[2]), "+f"(d[3]) \
                 : "r"(a[0]), "r"(a[1]), "r"(a[2]), "r"(a[3]), "r"(b0), "r"(b1))
#define CPCOMMIT() asm volatile("cp.async.commit_group;\n" ::)

__device__ __forceinline__ uint32_t packbf(float a, float b) {
    __nv_bfloat162 t = __floats2bfloat162_rn(a, b);
    return *(uint32_t*)&t;
}
__device__ __forceinline__ uint16_t packf8(float a, float b) {
    uint16_t r;
    asm("cvt.rn.satfinite.e4m3x2.f32 %0, %1, %2;" : "=h"(r) : "f"(b), "f"(a));
    return r;
}
__device__ __forceinline__ uint8_t f2f8(float v) {
    uint16_t r;
    asm("cvt.rn.satfinite.e4m3x2.f32 %0, %1, %2;" : "=h"(r) : "f"(0.f), "f"(v));
    return (uint8_t)(r & 0xFF);
}
__device__ __forceinline__ float ex2(float x) {
    float y;
    asm("ex2.approx.ftz.f32 %0, %1;" : "=f"(y) : "f"(x));
    return y;
}

// ---------------- prep: A -> bf16, B -> B^T bf16 ---------------------------
__global__ void __launch_bounds__(256) prep_kernel(
        __nv_bfloat16* __restrict__ abf, __nv_bfloat16* __restrict__ bt,
        const float* __restrict__ Aq, const float* __restrict__ Ao_,
        const float* __restrict__ A1_, const float* __restrict__ A2_,
        const float* __restrict__ Bq, const float* __restrict__ Bo_,
        const float* __restrict__ B1_, const float* __restrict__ B2_) {
    if (blockIdx.x < 448) {
        const size_t idx = ((size_t)blockIdx.x * 256 + threadIdx.x) * 2;
        float2 v;
        if (idx < 32768)       v = *(const float2*)(Aq  + idx);
        else if (idx < 65536)  v = *(const float2*)(Ao_ + idx - 32768);
        else if (idx < 98304)  v = *(const float2*)(A1_ + idx - 65536);
        else                   v = *(const float2*)(A2_ + idx - 98304);
        *(uint32_t*)(abf + idx) = packbf(v.x, v.y);
    } else {
        const int i = (blockIdx.x - 448) * 256 + threadIdx.x;
        const int j = i >> 5, r = i & 31;
        float v;
        if (j < 3072)       v = Bq [(size_t)r * 3072 + j];
        else if (j < 4096)  v = Bo_[(size_t)r * 1024 + (j - 3072)];
        else if (j < 12288) v = B1_[(size_t)r * 8192 + (j - 4096)];
        else                v = B2_[(size_t)r * 1024 + (j - 12288)];
        bt[i] = __float2bfloat16_rn(v);
    }
}

// ---------------- weff via bf16 tensor-core K=32 GEMM ----------------------
__global__ void __launch_bounds__(256, 2) weff_gemm(
        const __nv_bfloat16* __restrict__ abf, const __nv_bfloat16* __restrict__ bt,
        const float* __restrict__ Wq, const float* __restrict__ Wo_,
        const float* __restrict__ W1_, const float* __restrict__ W2_,
        uint8_t* __restrict__ o0, uint8_t* __restrict__ o1,
        uint8_t* __restrict__ o2, uint8_t* __restrict__ o3) {
    __shared__ __align__(16) char sm[2 * 10240];
    const uint32_t sX = (uint32_t)__cvta_generic_to_shared(sm);
    const uint32_t sY = sX + 10240;
    const int tid = threadIdx.x, lane = tid & 31, warp = tid >> 5;
    const int wm = warp >> 1, wn = warp & 1;
    const int bid = blockIdx.x;
    int which, tloc;
    if (bid < 192)      { which = 0; tloc = bid; }
    else if (bid < 256) { which = 1; tloc = bid - 192; }
    else if (bid < 768) { which = 2; tloc = bid - 256; }
    else                { which = 3; tloc = bid - 768; }
    const int KT = (which == 3) ? 32 : 8;
    const int Km = (which == 3) ? 4096 : 1024;
    const int bx = tloc % KT, by = tloc / KT;
    const int jb = (which == 0) ? 0 : (which == 1) ? 3072 : (which == 2) ? 4096 : 12288;
    const int db = which * 1024;
    const float* W = (which == 0) ? Wq : (which == 1) ? Wo_ : (which == 2) ? W1_ : W2_;
    uint8_t* out   = (which == 0) ? o0 : (which == 1) ? o1 : (which == 2) ? o2 : o3;

    #pragma unroll
    for (int i = 0; i < 2; ++i) {
        const int c = tid + i * 256;
        const int row = c >> 2, ch = c & 3;
        cp16(sX + row * 80 + ch * 16, bt  + ((size_t)(jb + by * 128 + row)) * 32 + ch * 8);
        cp16(sY + row * 80 + ch * 16, abf + ((size_t)(db + bx * 128 + row)) * 32 + ch * 8);
    }
    CPCOMMIT();
    asm volatile("cp.async.wait_group 0;" ::: "memory");
    __syncthreads();

    float acc[2][8][4];
    #pragma unroll
    for (int mi = 0; mi < 2; ++mi)
        #pragma unroll
        for (int ni = 0; ni < 8; ++ni)
            #pragma unroll
            for (int e = 0; e < 4; ++e) acc[mi][ni][e] = 0.f;

    const int lr = lane & 15, lh = lane >> 4;
    #pragma unroll
    for (int ks = 0; ks < 2; ++ks) {
        uint32_t a[2][4], b[4][4];
        #pragma unroll
        for (int mi = 0; mi < 2; ++mi)
            ldmx4(a[mi], sX + (wm * 32 + mi * 16 + lr) * 80 + ks * 32 + lh * 16);
        #pragma unroll
        for (int nj = 0; nj < 4; ++nj)
            ldmx4(b[nj], sY + (wn * 64 + nj * 16 + lr) * 80 + ks * 32 + lh * 16);
        #pragma unroll
        for (int mi = 0; mi < 2; ++mi)
            #pragma unroll
            for (int ni = 0; ni < 8; ++ni)
                MMA_BF16(acc[mi][ni], a[mi], b[ni >> 1][ni & 1], b[ni >> 1][(ni & 1) + 2]);
    }

    const int g = lane >> 2, tg = lane & 3;
    #pragma unroll
    for (int mi = 0; mi < 2; ++mi) {
        #pragma unroll
        for (int ni = 0; ni < 8; ++ni) {
            const int col = bx * 128 + wn * 64 + ni * 8 + tg * 2;
            #pragma unroll
            for (int half = 0; half < 2; ++half) {
                const int j = by * 128 + wm * 32 + mi * 16 + g + half * 8;
                const int jout = (which == 2)
                    ? ((j < DFF_) ? 2 * j : 2 * (j - DFF_) + 1) : j;
                const float2 wv = *(const float2*)(W + (size_t)j * Km + col);
                const float v0 = (wv.x + acc[mi][ni][2 * half]     * (1.f / 32.f)) * WSCALE;
                const float v1 = (wv.y + acc[mi][ni][2 * half + 1] * (1.f / 32.f)) * WSCALE;
                *(uint16_t*)(out + (size_t)jout * Km + col) = packf8(v0, v1);
            }
        }
    }
}

// ---------------- LayerNorm (one block per row, D=1024), fp8 out -----------
__global__ void __launch_bounds__(256) ln_kernel(const float* __restrict__ xin,
        const float* __restrict__ gw, const float* __restrict__ bw,
        uint8_t* __restrict__ y) {
    __shared__ float sred[64];
    const int row = blockIdx.x, tid = threadIdx.x;
    const float4 v = ((const float4*)(xin + (size_t)row * 1024))[tid];
    float s = v.x + v.y + v.z + v.w;
    float q = v.x * v.x + v.y * v.y + v.z * v.z + v.w * v.w;
    #pragma unroll
    for (int off = 16; off; off >>= 1) {
        s += __shfl_xor_sync(0xffffffffu, s, off);
        q += __shfl_xor_sync(0xffffffffu, q, off);
    }
    if ((tid & 31) == 0) { sred[tid >> 5] = s; sred[32 + (tid >> 5)] = q; }
    __syncthreads();
    s = 0.f; q = 0.f;
    #pragma unroll
    for (int i = 0; i < 8; ++i) { s += sred[i]; q += sred[32 + i]; }
    const float mu   = s * (1.f / 1024.f);
    const float var  = q * (1.f / 1024.f) - mu * mu;
    const float rstd = rsqrtf(var + 1e-6f);
    const float4 g4 = ((const float4*)gw)[tid];
    const float4 b4 = ((const float4*)bw)[tid];
    const float y0 = (v.x - mu) * rstd * g4.x + b4.x;
    const float y1 = (v.y - mu) * rstd * g4.y + b4.y;
    const float y2 = (v.z - mu) * rstd * g4.z + b4.z;
    const float y3 = (v.w - mu) * rstd * g4.w + b4.w;
    *(uint32_t*)(y + (size_t)row * 1024 + tid * 4) =
        (uint32_t)packf8(y0, y1) | ((uint32_t)packf8(y2, y3) << 16);
}

// ---------------- fp8 mma GEMM: C[M,N] = (A[M,K] * B[N,K]^T) * DEQ ---------
#define GSTG 4
#define GSTAGE_BYTES 20480

template <int EPI>
__global__ void __launch_bounds__(256, 2) gemm_fp8_nt(
        const uint8_t* __restrict__ A, const uint8_t* __restrict__ B,
        void* __restrict__ Cout, const void* __restrict__ aux1,
        const void* __restrict__ aux2, int M, int N, int K) {
    extern __shared__ char smem[];
    const uint32_t sbase = (uint32_t)__cvta_generic_to_shared(smem);
    const int tid = threadIdx.x, lane = tid & 31, warp = tid >> 5;
    const int wm = warp >> 1, wn = warp & 1;
    const int bm = blockIdx.y, bn = blockIdx.x;
    const uint8_t* Ab = A + (size_t)bm * 128 * K;
    const uint8_t* Bb = B + (size_t)bn * 128 * K;
    const int NKT = K >> 6;

    const int r0 = tid >> 2, fof = (tid & 3) * 16;
    const int r1 = r0 + 64;

    auto issue = [&](int st, int kt) {
        const uint32_t sA = sbase + st * GSTAGE_BYTES;
        const uint32_t sB = sA + 10240;
        const int kof = kt * 64;
        cp16(sA + r0 * 80 + fof, Ab + (size_t)r0 * K + kof + fof);
        cp16(sA + r1 * 80 + fof, Ab + (size_t)r1 * K + kof + fof);
        cp16(sB + r0 * 80 + fof, Bb + (size_t)r0 * K + kof + fof);
        cp16(sB + r1 * 80 + fof, Bb + (size_t)r1 * K + kof + fof);
        CPCOMMIT();
    };

    #pragma unroll
    for (int s = 0; s < GSTG - 1; ++s) issue(s, s);

    float acc[2][8][4];
    #pragma unroll
    for (int mi = 0; mi < 2; ++mi)
        #pragma unroll
        for (int ni = 0; ni < 8; ++ni)
            #pragma unroll
            for (int e = 0; e < 4; ++e) acc[mi][ni][e] = 0.f;

    const int lr = lane & 15, lh = lane >> 4;

    for (int kt = 0; kt < NKT; ++kt) {
        asm volatile("cp.async.wait_group %0;\n" :: "n"(GSTG - 2));
        __syncthreads();
        if (kt + GSTG - 1 < NKT) issue((kt + GSTG - 1) & (GSTG - 1), kt + GSTG - 1);
        else CPCOMMIT();

        const uint32_t sA = sbase + (kt & (GSTG - 1)) * GSTAGE_BYTES;
        const uint32_t sB = sA + 10240;
        #pragma unroll
        for (int ks = 0; ks < 2; ++ks) {
            uint32_t a[2][4], b[4][4];
            #pragma unroll
            for (int mi = 0; mi < 2; ++mi)
                ldmx4(a[mi], sA + (wm * 32 + mi * 16 + lr) * 80 + ks * 32 + lh * 16);
            #pragma unroll
            for (int nj = 0; nj < 4; ++nj)
                ldmx4(b[nj], sB + (wn * 64 + nj * 16 + lr) * 80 + ks * 32 + lh * 16);
            #pragma unroll
            for (int mi = 0; mi < 2; ++mi)
                #pragma unroll
                for (int ni = 0; ni < 8; ++ni)
                    MMA_FP8(acc[mi][ni], a[mi], b[ni >> 1][ni & 1], b[ni >> 1][(ni & 1) + 2]);
        }
    }

    const int g = lane >> 2, tg = lane & 3;
    #pragma unroll
    for (int mi = 0; mi < 2; ++mi) {
        const int row = bm * 128 + wm * 32 + mi * 16 + g;
        #pragma unroll
        for (int ni = 0; ni < 8; ++ni) {
            const int col = bn * 128 + wn * 64 + ni * 8 + tg * 2;
            if constexpr (EPI == 1) {
                uint8_t* C = (uint8_t*)Cout;
                const int oc = col >> 1;
                const int oN = N >> 1;
                const float gt0 = acc[mi][ni][0] * DEQ, at0 = acc[mi][ni][1] * DEQ;
                const float gt1 = acc[mi][ni][2] * DEQ, at1 = acc[mi][ni][3] * DEQ;
                C[(size_t)row * oN + oc]       = f2f8(gt0 / (1.f + __expf(-gt0)) * at0);
                C[(size_t)(row + 8) * oN + oc] = f2f8(gt1 / (1.f + __expf(-gt1)) * at1);
            } else if constexpr (EPI == 2) {
                float* C = (float*)Cout;
                const float* resid = (const float*)aux1;
                const float* ls    = (const float*)aux2;
                const float2 lv = *(const float2*)(ls + col);
                const float2 x0 = *(const float2*)(resid + (size_t)row * N + col);
                const float2 x1 = *(const float2*)(resid + (size_t)(row + 8) * N + col);
                *(float2*)(C + (size_t)row * N + col) =
                    make_float2(x0.x + lv.x * acc[mi][ni][0] * DEQ,
                                x0.y + lv.y * acc[mi][ni][1] * DEQ);
                *(float2*)(C + (size_t)(row + 8) * N + col) =
                    make_float2(x1.x + lv.x * acc[mi][ni][2] * DEQ,
                                x1.y + lv.y * acc[mi][ni][3] * DEQ);
            } else {  // EPI == 3: qkv split
                if (col < 2048) {
                    uint8_t* dst = (uint8_t*)(col < 1024 ? Cout : (void*)aux1);
                    const int c = col & 1023;
                    *(uint16_t*)(dst + (size_t)row * 1024 + c) =
                        packf8(acc[mi][ni][0] * (DEQ * QS), acc[mi][ni][1] * (DEQ * QS));
                    *(uint16_t*)(dst + (size_t)(row + 8) * 1024 + c) =
                        packf8(acc[mi][ni][2] * (DEQ * QS), acc[mi][ni][3] * (DEQ * QS));
                } else {
                    __nv_bfloat16* v = (__nv_bfloat16*)aux2;
                    const int c = col - 2048;
                    *(uint32_t*)(v + (size_t)row * 1024 + c) =
                        packbf(acc[mi][ni][0] * DEQ, acc[mi][ni][1] * DEQ);
                    *(uint32_t*)(v + (size_t)(row + 8) * 1024 + c) =
                        packbf(acc[mi][ni][2] * DEQ, acc[mi][ni][3] * DEQ);
                }
            }
        }
    }
}

// ---------------- flash attention: diagonal-first tiles, fp8 QK^T ----------
// Descending kt => first tile holds the row max; rescale is skipped via
// warp-uniform vote on later tiles. 4-stage KV ring, single barrier/tile.
#define AKV_STAGE 14336
#define ATTN_SMEM (10240 + 4 * AKV_STAGE)

__global__ void __launch_bounds__(256, 2) attn_tc(
        const uint8_t* __restrict__ q8, const uint8_t* __restrict__ k8,
        const __nv_bfloat16* __restrict__ vbf, uint8_t* __restrict__ outp) {
    extern __shared__ char smraw[];
    const uint32_t sQ = (uint32_t)__cvta_generic_to_shared(smraw);
    const int qt = (int)(gridDim.x - 1 - blockIdx.x);
    const int h = blockIdx.y, b = blockIdx.z;
    const int tid = threadIdx.x, lane = tid & 31, w = tid >> 5;
    const int g = lane >> 2, tg = lane & 3;
    const int lr = lane & 15, lh = lane >> 4;
    const float slope2 = exp2f(-0.5f * (float)(h + 1)) * LOG2E;
    const size_t rowbase = (size_t)b * SEQ;

    #pragma unroll
    for (int i = 0; i < 2; ++i) {
        const int c = tid + i * 256;
        const int row = c >> 2, off = (c & 3) * 16;
        cp16(sQ + row * 80 + off,
             q8 + (rowbase + qt * 128 + row) * 1024 + h * 64 + off);
    }
    CPCOMMIT();

    const int ktmax = 2 * qt + 1;
    auto issueKV = [&](int kt) {
        const uint32_t sK = sQ + 10240 + (kt & 3) * AKV_STAGE;
        const uint32_t sV = sK + 5120;
        {
            const int row = tid >> 2, off = (tid & 3) * 16;
            cp16(sK + row * 80 + off,
                 k8 + (rowbase + kt * 64 + row) * 1024 + h * 64 + off);
        }
        #pragma unroll
        for (int i = 0; i < 2; ++i) {
            const int c = tid + i * 256;
            const int row = c >> 3, off = (c & 7) * 8;
            cp16(sV + row * 144 + off * 2,
                 vbf + (rowbase + kt * 64 + row) * 1024 + h * 64 + off);
        }
        CPCOMMIT();
    };
    // descending prefetch: ktmax, ktmax-1, ktmax-2
    issueKV(ktmax);
    issueKV(ktmax - 1);               // ktmax >= 1 always
    if (ktmax >= 2) issueKV(ktmax - 2); else CPCOMMIT();

    asm volatile("cp.async.wait_group %0;\n" :: "n"(3));
    __syncthreads();
    uint32_t qa[2][4];
    #pragma unroll
    for (int ks = 0; ks < 2; ++ks)
        ldmx4(qa[ks], sQ + (w * 16 + lr) * 80 + ks * 32 + lh * 16);

    float o[8][4];
    #pragma unroll
    for (int ni = 0; ni < 8; ++ni)
        #pragma unroll
        for (int e = 0; e < 4; ++e) o[ni][e] = 0.f;
    float m0 = -1e30f, m1 = -1e30f, l0 = 0.f, l1 = 0.f;

    const int qr0 = qt * 128 + w * 16 + g;
    const int qwmin = qt * 128 + w * 16;
    const int qwmax = qwmin + 15;

    for (int kt = ktmax; kt >= 0; --kt) {
        asm volatile("cp.async.wait_group %0;\n" :: "n"(2));
        __syncthreads();
        if (kt * 64 <= qwmax) {
            const uint32_t sK = sQ + 10240 + (kt & 3) * AKV_STAGE;
            const uint32_t sV = sK + 5120;
            float sc[8][4];
            #pragma unroll
            for (int ni = 0; ni < 8; ++ni)
                #pragma unroll
                for (int e = 0; e < 4; ++e) sc[ni][e] = 0.f;
            #pragma unroll
            for (int ks = 0; ks < 2; ++ks) {
                uint32_t kb[4][4];
                #pragma unroll
                for (int nj = 0; nj < 4; ++nj)
                    ldmx4(kb[nj], sK + (nj * 16 + lr) * 80 + ks * 32 + lh * 16);
                #pragma unroll
                for (int ni = 0; ni < 8; ++ni)
                    MMA_FP8(sc[ni], qa[ks], kb[ni >> 1][ni & 1], kb[ni >> 1][(ni & 1) + 2]);
            }
            #pragma unroll
            for (int ni = 0; ni < 8; ++ni) {
                const float kcf = (float)(kt * 64 + ni * 8 + tg * 2);
                const float b0 = slope2 * kcf;
                const float b1 = slope2 * (kcf + 1.f);
                sc[ni][0] = sc[ni][0] * ATTN_SCL2 + b0;
                sc[ni][1] = sc[ni][1] * ATTN_SCL2 + b1;
                sc[ni][2] = sc[ni][2] * ATTN_SCL2 + b0;
                sc[ni][3] = sc[ni][3] * ATTN_SCL2 + b1;
            }
            if ((kt * 64 + 63) > qwmin) {
                #pragma unroll
                for (int ni = 0; ni < 8; ++ni) {
                    const int kc = kt * 64 + ni * 8 + tg * 2;
                    #pragma unroll
                    for (int e = 0; e < 4; ++e) {
                        const int q = (e < 2) ? qr0 : qr0 + 8;
                        if (kc + (e & 1) > q) sc[ni][e] = -1e30f;
                    }
                }
            }
            float rm0 = -1e30f, rm1 = -1e30f;
            #pragma unroll
            for (int ni = 0; ni < 8; ++ni) {
                rm0 = fmaxf(rm0, fmaxf(sc[ni][0], sc[ni][1]));
                rm1 = fmaxf(rm1, fmaxf(sc[ni][2], sc[ni][3]));
            }
            rm0 = fmaxf(rm0, __shfl_xor_sync(0xffffffffu, rm0, 1));
            rm0 = fmaxf(rm0, __shfl_xor_sync(0xffffffffu, rm0, 2));
            rm1 = fmaxf(rm1, __shfl_xor_sync(0xffffffffu, rm1, 1));
            rm1 = fmaxf(rm1, __shfl_xor_sync(0xffffffffu, rm1, 2));
            const float mn0 = fmaxf(m0, rm0), mn1 = fmaxf(m1, rm1);
            const bool stable = (mn0 == m0) && (mn1 == m1);
            if (!__all_sync(0xffffffffu, stable)) {
                const float cs0 = ex2(m0 - mn0), cs1 = ex2(m1 - mn1);
                l0 *= cs0; l1 *= cs1;
                m0 = mn0; m1 = mn1;
                #pragma unroll
                for (int ni = 0; ni < 8; ++ni) {
                    o[ni][0] *= cs0; o[ni][1] *= cs0;
                    o[ni][2] *= cs1; o[ni][3] *= cs1;
                }
            }
            float ps0 = 0.f, ps1 = 0.f;
            #pragma unroll
            for (int ni = 0; ni < 8; ++ni) {
                sc[ni][0] = ex2(sc[ni][0] - m0); ps0 += sc[ni][0];
                sc[ni][1] = ex2(sc[ni][1] - m0); ps0 += sc[ni][1];
                sc[ni][2] = ex2(sc[ni][2] - m1); ps1 += sc[ni][2];
                sc[ni][3] = ex2(sc[ni][3] - m1); ps1 += sc[ni][3];
            }
            ps0 += __shfl_xor_sync(0xffffffffu, ps0, 1);
            ps0 += __shfl_xor_sync(0xffffffffu, ps0, 2);
            ps1 += __shfl_xor_sync(0xffffffffu, ps1, 1);
            ps1 += __shfl_xor_sync(0xffffffffu, ps1, 2);
            l0 += ps0; l1 += ps1;
            #pragma unroll
            for (int j = 0; j < 4; ++j) {
                uint32_t pa[4];
                pa[0] = packbf(sc[2 * j][0],     sc[2 * j][1]);
                pa[1] = packbf(sc[2 * j][2],     sc[2 * j][3]);
                pa[2] = packbf(sc[2 * j + 1][0], sc[2 * j + 1][1]);
                pa[3] = packbf(sc[2 * j + 1][2], sc[2 * j + 1][3]);
                #pragma unroll
                for (int nt = 0; nt < 4; ++nt) {
                    uint32_t vb[4];
                    ldmx4t(vb, sV + ((j * 16 + (lane & 7) + ((lane >> 3) & 1) * 8) * 144)
                                  + (nt * 16 + ((lane >> 4) & 1) * 8) * 2);
                    MMA_BF16(o[2 * nt],     pa, vb[0], vb[1]);
                    MMA_BF16(o[2 * nt + 1], pa, vb[2], vb[3]);
                }
            }
        }
        if (kt - 3 >= 0) issueKV(kt - 3);
        else CPCOMMIT();
    }

    const float inv0 = 1.f / l0, inv1 = 1.f / l1;
    const size_t row0 = rowbase + qr0;
    #pragma unroll
    for (int ni = 0; ni < 8; ++ni) {
        const int col = h * 64 + ni * 8 + tg * 2;
        *(uint16_t*)(outp + row0 * D_MODEL + col) =
            packf8(o[ni][0] * inv0, o[ni][1] * inv0);
        *(uint16_t*)(outp + (row0 + 8) * D_MODEL + col) =
            packf8(o[ni][2] * inv1, o[ni][3] * inv1);
    }
}

// ---------------- launch ---------------------------------------------------
extern "C" void kernel_launch(void* const* d_in, const int* in_sizes, int n_in,
                              void* d_out, int out_size) {
    (void)in_sizes; (void)n_in; (void)out_size;
    const float* x    = (const float*)d_in[0];
    const float* ln1g = (const float*)d_in[2];
    const float* ln1b = (const float*)d_in[3];
    const float* Wqkv = (const float*)d_in[4];
    const float* Aqkv = (const float*)d_in[5];
    const float* Bqkv = (const float*)d_in[6];
    const float* Wo   = (const float*)d_in[7];
    const float* Ao   = (const float*)d_in[8];
    const float* Bo   = (const float*)d_in[9];
    const float* ln2g = (const float*)d_in[10];
    const float* ln2b = (const float*)d_in[11];
    const float* W1   = (const float*)d_in[12];
    const float* A1   = (const float*)d_in[13];
    const float* B1   = (const float*)d_in[14];
    const float* W2   = (const float*)d_in[15];
    const float* A2   = (const float*)d_in[16];
    const float* B2   = (const float*)d_in[17];
    const float* ls1  = (const float*)d_in[18];
    const float* ls2  = (const float*)d_in[19];
    float* out = (float*)d_out;

    uint8_t *p_xn, *p_attn, *p_ffin, *p_q8, *p_k8;
    uint8_t *p_weqkv, *p_weo, *p_we1, *p_we2;
    __nv_bfloat16 *p_v, *p_abf, *p_bt;
    float *p_x1;
    cudaGetSymbolAddress((void**)&p_xn,    g_xn8);
    cudaGetSymbolAddress((void**)&p_attn,  g_attn8);
    cudaGetSymbolAddress((void**)&p_ffin,  g_ffin8);
    cudaGetSymbolAddress((void**)&p_q8,    g_q8);
    cudaGetSymbolAddress((void**)&p_k8,    g_k8);
    cudaGetSymbolAddress((void**)&p_v,     g_v_bf);
    cudaGetSymbolAddress((void**)&p_x1,    g_x1);
    cudaGetSymbolAddress((void**)&p_weqkv, g_weqkv);
    cudaGetSymbolAddress((void**)&p_weo,   g_weo);
    cudaGetSymbolAddress((void**)&p_we1,   g_we1);
    cudaGetSymbolAddress((void**)&p_we2,   g_we2);
    cudaGetSymbolAddress((void**)&p_abf,   g_abf);
    cudaGetSymbolAddress((void**)&p_bt,    g_bt);

    const int smem_gemm = GSTG * GSTAGE_BYTES;   // 81920
    cudaFuncSetAttribute((const void*)gemm_fp8_nt<1>, cudaFuncAttributeMaxDynamicSharedMemorySize, smem_gemm);
    cudaFuncSetAttribute((const void*)gemm_fp8_nt<2>, cudaFuncAttributeMaxDynamicSharedMemorySize, smem_gemm);
    cudaFuncSetAttribute((const void*)gemm_fp8_nt<3>, cudaFuncAttributeMaxDynamicSharedMemorySize, smem_gemm);
    cudaFuncSetAttribute((const void*)attn_tc,        cudaFuncAttributeMaxDynamicSharedMemorySize, ATTN_SMEM);

    // 1: prep (A->bf16, B->B^T bf16)
    prep_kernel<<<2112, 256>>>(p_abf, p_bt, Aqkv, Ao, A1, A2, Bqkv, Bo, B1, B2);
    // 2: LN1
    ln_kernel<<<NTOK, 256>>>(x, ln1g, ln1b, p_xn);
    // 3: weff via tensor-core GEMM
    weff_gemm<<<1024, 256>>>(p_abf, p_bt, Wqkv, Wo, W1, W2,
                             p_weqkv, p_weo, p_we1, p_we2);
    // 4: qkv GEMM (profiled slot)
    gemm_fp8_nt<3><<<dim3(3072 / 128, NTOK / 128), 256, smem_gemm>>>(
        p_xn, p_weqkv, p_q8, p_k8, p_v, NTOK, 3072, 1024);
    // 5: attention
    attn_tc<<<dim3(SEQ / 128, NH, 2), 256, ATTN_SMEM>>>(p_q8, p_k8, p_v, p_attn);
    // 6: o-proj + residual
    gemm_fp8_nt<2><<<dim3(1024 / 128, NTOK / 128), 256, smem_gemm>>>(
        p_attn, p_weo, p_x1, x, ls1, NTOK, 1024, 1024);
    // 7: LN2
    ln_kernel<<<NTOK, 256>>>(p_x1, ln2g, ln2b, p_xn);
    // 8: W1 + swiglu
    gemm_fp8_nt<1><<<dim3(8192 / 128, NTOK / 128), 256, smem_gemm>>>(
        p_xn, p_we1, p_ffin, nullptr, nullptr, NTOK, 8192, 1024);
    // 9: W2 + residual -> out
    gemm_fp8_nt<2><<<dim3(1024 / 128, NTOK / 128), 256, smem_gemm>>>(
        p_ffin, p_we2, out, p_x1, ls2, NTOK, 1024, 4096);
}

// round 15
// speedup vs baseline: 1.0628x; 1.0528x over previous
#include <cuda_runtime.h>
#include <cuda_bf16.h>
#include <cstdint>

#define D_MODEL 1024
#define NTOK    4096
#define DFF_    4096
#define SEQ     2048
#define NH      16

// ---------------- scratch (device globals: allocation-free) ----------------
__device__ uint8_t       g_xn8    [(size_t)NTOK * D_MODEL];          // fp8 e4m3
__device__ uint8_t       g_attn8  [(size_t)NTOK * D_MODEL];          // fp8
__device__ uint8_t       g_ffin8  [(size_t)NTOK * DFF_];             // fp8
__device__ uint8_t       g_q8     [(size_t)NTOK * D_MODEL];          // fp8 x4
__device__ uint8_t       g_k8     [(size_t)NTOK * D_MODEL];          // fp8 x4
__device__ __nv_bfloat16 g_v_bf   [(size_t)NTOK * D_MODEL];
__device__ float         g_x1     [(size_t)NTOK * D_MODEL];
__device__ uint8_t       g_weqkv  [(size_t)3 * D_MODEL * D_MODEL];   // fp8 x64
__device__ uint8_t       g_weo    [(size_t)D_MODEL * D_MODEL];
__device__ uint8_t       g_we1    [(size_t)2 * DFF_ * D_MODEL];
__device__ uint8_t       g_we2    [(size_t)D_MODEL * DFF_];
__device__ __nv_bfloat16 g_abf    [(size_t)7168 * 32];               // A mats bf16
__device__ __nv_bfloat16 g_bt     [(size_t)13312 * 32];              // B^T mats bf16

#define WSCALE 64.0f
#define DEQ    (1.0f / 64.0f)
#define QS     4.0f
#define LOG2E  1.44269504f
#define ATTN_SCL2 (0.125f / 16.0f * LOG2E)

// ---------------- PTX helpers ----------------------------------------------
__device__ __forceinline__ void cp16(uint32_t s, const void* g) {
    asm volatile("cp.async.cg.shared.global [%0], [%1], 16;\n" :: "r"(s), "l"(g));
}
__device__ __forceinline__ void ldmx4(uint32_t* r, uint32_t addr) {
    asm volatile("ldmatrix.sync.aligned.m8n8.x4.shared.b16 {%0,%1,%2,%3}, [%4];"
                 : "=r"(r[0]), "=r"(r[1]), "=r"(r[2]), "=r"(r[3]) : "r"(addr));
}
__device__ __forceinline__ void ldmx4t(uint32_t* r, uint32_t addr) {
    asm volatile("ldmatrix.sync.aligned.m8n8.x4.trans.shared.b16 {%0,%1,%2,%3}, [%4];"
                 : "=r"(r[0]), "=r"(r[1]), "=r"(r[2]), "=r"(r[3]) : "r"(addr));
}
#define MMA_BF16(d, a, b0, b1) \
    asm volatile("mma.sync.aligned.m16n8k16.row.col.f32.bf16.bf16.f32 " \
                 "{%0,%1,%2,%3}, {%4,%5,%6,%7}, {%8,%9}, {%0,%1,%2,%3};" \
                 : "+f"(d[0]), "+f"(d[1]), "+f"(d[2]), "+f"(d[3]) \
                 : "r"(a[0]), "r"(a[1]), "r"(a[2]), "r"(a[3]), "r"(b0), "r"(b1))
#define MMA_FP8(d, a, b0, b1) \
    asm volatile("mma.sync.aligned.m16n8k32.row.col.f32.e4m3.e4m3.f32 " \
                 "{%0,%1,%2,%3}, {%4,%5,%6,%7}, {%8,%9}, {%0,%1,%2,%3};" \
                 : "+f"(d[0]), "+f"(d[1]), "+f"(d[2]), "+f"(d[3]) \
                 : "r"(a[0]), "r"(a[1]), "r"(a[2]), "r"(a[3]), "r"(b0), "r"(b1))
#define CPCOMMIT() asm volatile("cp.async.commit_group;\n" ::)

__device__ __forceinline__ uint32_t packbf(float a, float b) {
    __nv_bfloat162 t = __floats2bfloat162_rn(a, b);
    return *(uint32_t*)&t;
}
__device__ __forceinline__ uint16_t packf8(float a, float b) {
    uint16_t r;
    asm("cvt.rn.satfinite.e4m3x2.f32 %0, %1, %2;" : "=h"(r) : "f"(b), "f"(a));
    return r;
}
__device__ __forceinline__ uint8_t f2f8(float v) {
    uint16_t r;
    asm("cvt.rn.satfinite.e4m3x2.f32 %0, %1, %2;" : "=h"(r) : "f"(0.f), "f"(v));
    return (uint8_t)(r & 0xFF);
}
__device__ __forceinline__ float ex2(float x) {
    float y;
    asm("ex2.approx.ftz.f32 %0, %1;" : "=f"(y) : "f"(x));
    return y;
}

// ---------------- prep: A -> bf16, B -> B^T bf16 ---------------------------
__global__ void __launch_bounds__(256) prep_kernel(
        __nv_bfloat16* __restrict__ abf, __nv_bfloat16* __restrict__ bt,
        const float* __restrict__ Aq, const float* __restrict__ Ao_,
        const float* __restrict__ A1_, const float* __restrict__ A2_,
        const float* __restrict__ Bq, const float* __restrict__ Bo_,
        const float* __restrict__ B1_, const float* __restrict__ B2_) {
    if (blockIdx.x < 448) {
        const size_t idx = ((size_t)blockIdx.x * 256 + threadIdx.x) * 2;
        float2 v;
        if (idx < 32768)       v = *(const float2*)(Aq  + idx);
        else if (idx < 65536)  v = *(const float2*)(Ao_ + idx - 32768);
        else if (idx < 98304)  v = *(const float2*)(A1_ + idx - 65536);
        else                   v = *(const float2*)(A2_ + idx - 98304);
        *(uint32_t*)(abf + idx) = packbf(v.x, v.y);
    } else {
        const int i = (blockIdx.x - 448) * 256 + threadIdx.x;
        const int j = i >> 5, r = i & 31;
        float v;
        if (j < 3072)       v = Bq [(size_t)r * 3072 + j];
        else if (j < 4096)  v = Bo_[(size_t)r * 1024 + (j - 3072)];
        else if (j < 12288) v = B1_[(size_t)r * 8192 + (j - 4096)];
        else                v = B2_[(size_t)r * 1024 + (j - 12288)];
        bt[i] = __float2bfloat16_rn(v);
    }
}

// ---------------- weff via bf16 tensor-core K=32 GEMM ----------------------
__global__ void __launch_bounds__(256, 2) weff_gemm(
        const __nv_bfloat16* __restrict__ abf, const __nv_bfloat16* __restrict__ bt,
        const float* __restrict__ Wq, const float* __restrict__ Wo_,
        const float* __restrict__ W1_, const float* __restrict__ W2_,
        uint8_t* __restrict__ o0, uint8_t* __restrict__ o1,
        uint8_t* __restrict__ o2, uint8_t* __restrict__ o3) {
    __shared__ __align__(16) char sm[2 * 10240];
    const uint32_t sX = (uint32_t)__cvta_generic_to_shared(sm);
    const uint32_t sY = sX + 10240;
    const int tid = threadIdx.x, lane = tid & 31, warp = tid >> 5;
    const int wm = warp >> 1, wn = warp & 1;
    const int bid = blockIdx.x;
    int which, tloc;
    if (bid < 192)      { which = 0; tloc = bid; }
    else if (bid < 256) { which = 1; tloc = bid - 192; }
    else if (bid < 768) { which = 2; tloc = bid - 256; }
    else                { which = 3; tloc = bid - 768; }
    const int KT = (which == 3) ? 32 : 8;
    const int Km = (which == 3) ? 4096 : 1024;
    const int bx = tloc % KT, by = tloc / KT;
    const int jb = (which == 0) ? 0 : (which == 1) ? 3072 : (which == 2) ? 4096 : 12288;
    const int db = which * 1024;
    const float* W = (which == 0) ? Wq : (which == 1) ? Wo_ : (which == 2) ? W1_ : W2_;
    uint8_t* out   = (which == 0) ? o0 : (which == 1) ? o1 : (which == 2) ? o2 : o3;

    #pragma unroll
    for (int i = 0; i < 2; ++i) {
        const int c = tid + i * 256;
        const int row = c >> 2, ch = c & 3;
        cp16(sX + row * 80 + ch * 16, bt  + ((size_t)(jb + by * 128 + row)) * 32 + ch * 8);
        cp16(sY + row * 80 + ch * 16, abf + ((size_t)(db + bx * 128 + row)) * 32 + ch * 8);
    }
    CPCOMMIT();
    asm volatile("cp.async.wait_group 0;" ::: "memory");
    __syncthreads();

    float acc[2][8][4];
    #pragma unroll
    for (int mi = 0; mi < 2; ++mi)
        #pragma unroll
        for (int ni = 0; ni < 8; ++ni)
            #pragma unroll
            for (int e = 0; e < 4; ++e) acc[mi][ni][e] = 0.f;

    const int lr = lane & 15, lh = lane >> 4;
    #pragma unroll
    for (int ks = 0; ks < 2; ++ks) {
        uint32_t a[2][4], b[4][4];
        #pragma unroll
        for (int mi = 0; mi < 2; ++mi)
            ldmx4(a[mi], sX + (wm * 32 + mi * 16 + lr) * 80 + ks * 32 + lh * 16);
        #pragma unroll
        for (int nj = 0; nj < 4; ++nj)
            ldmx4(b[nj], sY + (wn * 64 + nj * 16 + lr) * 80 + ks * 32 + lh * 16);
        #pragma unroll
        for (int mi = 0; mi < 2; ++mi)
            #pragma unroll
            for (int ni = 0; ni < 8; ++ni)
                MMA_BF16(acc[mi][ni], a[mi], b[ni >> 1][ni & 1], b[ni >> 1][(ni & 1) + 2]);
    }

    const int g = lane >> 2, tg = lane & 3;
    #pragma unroll
    for (int mi = 0; mi < 2; ++mi) {
        #pragma unroll
        for (int ni = 0; ni < 8; ++ni) {
            const int col = bx * 128 + wn * 64 + ni * 8 + tg * 2;
            #pragma unroll
            for (int half = 0; half < 2; ++half) {
                const int j = by * 128 + wm * 32 + mi * 16 + g + half * 8;
                const int jout = (which == 2)
                    ? ((j < DFF_) ? 2 * j : 2 * (j - DFF_) + 1) : j;
                const float2 wv = *(const float2*)(W + (size_t)j * Km + col);
                const float v0 = (wv.x + acc[mi][ni][2 * half]     * (1.f / 32.f)) * WSCALE;
                const float v1 = (wv.y + acc[mi][ni][2 * half + 1] * (1.f / 32.f)) * WSCALE;
                *(uint16_t*)(out + (size_t)jout * Km + col) = packf8(v0, v1);
            }
        }
    }
}

// ---------------- LayerNorm (one block per row, D=1024), fp8 out -----------
__global__ void __launch_bounds__(256) ln_kernel(const float* __restrict__ xin,
        const float* __restrict__ gw, const float* __restrict__ bw,
        uint8_t* __restrict__ y) {
    __shared__ float sred[64];
    const int row = blockIdx.x, tid = threadIdx.x;
    const float4 v = ((const float4*)(xin + (size_t)row * 1024))[tid];
    float s = v.x + v.y + v.z + v.w;
    float q = v.x * v.x + v.y * v.y + v.z * v.z + v.w * v.w;
    #pragma unroll
    for (int off = 16; off; off >>= 1) {
        s += __shfl_xor_sync(0xffffffffu, s, off);
        q += __shfl_xor_sync(0xffffffffu, q, off);
    }
    if ((tid & 31) == 0) { sred[tid >> 5] = s; sred[32 + (tid >> 5)] = q; }
    __syncthreads();
    s = 0.f; q = 0.f;
    #pragma unroll
    for (int i = 0; i < 8; ++i) { s += sred[i]; q += sred[32 + i]; }
    const float mu   = s * (1.f / 1024.f);
    const float var  = q * (1.f / 1024.f) - mu * mu;
    const float rstd = rsqrtf(var + 1e-6f);
    const float4 g4 = ((const float4*)gw)[tid];
    const float4 b4 = ((const float4*)bw)[tid];
    const float y0 = (v.x - mu) * rstd * g4.x + b4.x;
    const float y1 = (v.y - mu) * rstd * g4.y + b4.y;
    const float y2 = (v.z - mu) * rstd * g4.z + b4.z;
    const float y3 = (v.w - mu) * rstd * g4.w + b4.w;
    *(uint32_t*)(y + (size_t)row * 1024 + tid * 4) =
        (uint32_t)packf8(y0, y1) | ((uint32_t)packf8(y2, y3) << 16);
}

// ---------------- fp8 mma GEMM: C[M,N] = (A[M,K] * B[N,K]^T) * DEQ ---------
// CTA tile 128x128, BK=128 fp8 (144B row stride), 3-stage cp.async,
// 256 threads = 8 warps (4m x 2n), warp tile 32x64, 2 CTAs/SM.
#define GSTG 3
#define GSTAGE_BYTES 36864   // (128+128) rows x 144B

template <int EPI>
__global__ void __launch_bounds__(256, 2) gemm_fp8_nt(
        const uint8_t* __restrict__ A, const uint8_t* __restrict__ B,
        void* __restrict__ Cout, const void* __restrict__ aux1,
        const void* __restrict__ aux2, int M, int N, int K) {
    extern __shared__ char smem[];
    const uint32_t sbase = (uint32_t)__cvta_generic_to_shared(smem);
    const int tid = threadIdx.x, lane = tid & 31, warp = tid >> 5;
    const int wm = warp >> 1, wn = warp & 1;
    const int bm = blockIdx.y, bn = blockIdx.x;
    const uint8_t* Ab = A + (size_t)bm * 128 * K;
    const uint8_t* Bb = B + (size_t)bn * 128 * K;
    const int NKT = K >> 7;

    const int rr = tid >> 3, rof = (tid & 7) * 16;   // 32 rows/pass, 8 chunks/row

    auto issue = [&](int st, int kt) {
        const uint32_t sA = sbase + st * GSTAGE_BYTES;
        const uint32_t sB = sA + 18432;
        const int kof = kt * 128;
        #pragma unroll
        for (int i = 0; i < 4; ++i) {
            const int row = rr + i * 32;
            cp16(sA + row * 144 + rof, Ab + (size_t)row * K + kof + rof);
            cp16(sB + row * 144 + rof, Bb + (size_t)row * K + kof + rof);
        }
        CPCOMMIT();
    };

    issue(0, 0);
    issue(1, 1);

    float acc[2][8][4];
    #pragma unroll
    for (int mi = 0; mi < 2; ++mi)
        #pragma unroll
        for (int ni = 0; ni < 8; ++ni)
            #pragma unroll
            for (int e = 0; e < 4; ++e) acc[mi][ni][e] = 0.f;

    const int lr = lane & 15, lh = lane >> 4;
    int st_use = 0, st_fill = 2;

    for (int kt = 0; kt < NKT; ++kt) {
        asm volatile("cp.async.wait_group %0;\n" :: "n"(GSTG - 2));
        __syncthreads();
        if (kt + 2 < NKT) issue(st_fill, kt + 2);
        else CPCOMMIT();
        st_fill = (st_fill == 2) ? 0 : st_fill + 1;

        const uint32_t sA = sbase + st_use * GSTAGE_BYTES;
        const uint32_t sB = sA + 18432;
        st_use = (st_use == 2) ? 0 : st_use + 1;
        #pragma unroll
        for (int ks = 0; ks < 4; ++ks) {
            uint32_t a[2][4], b[4][4];
            #pragma unroll
            for (int mi = 0; mi < 2; ++mi)
                ldmx4(a[mi], sA + (wm * 32 + mi * 16 + lr) * 144 + ks * 32 + lh * 16);
            #pragma unroll
            for (int nj = 0; nj < 4; ++nj)
                ldmx4(b[nj], sB + (wn * 64 + nj * 16 + lr) * 144 + ks * 32 + lh * 16);
            #pragma unroll
            for (int mi = 0; mi < 2; ++mi)
                #pragma unroll
                for (int ni = 0; ni < 8; ++ni)
                    MMA_FP8(acc[mi][ni], a[mi], b[ni >> 1][ni & 1], b[ni >> 1][(ni & 1) + 2]);
        }
    }

    const int g = lane >> 2, tg = lane & 3;
    #pragma unroll
    for (int mi = 0; mi < 2; ++mi) {
        const int row = bm * 128 + wm * 32 + mi * 16 + g;
        #pragma unroll
        for (int ni = 0; ni < 8; ++ni) {
            const int col = bn * 128 + wn * 64 + ni * 8 + tg * 2;
            if constexpr (EPI == 1) {
                uint8_t* C = (uint8_t*)Cout;
                const int oc = col >> 1;
                const int oN = N >> 1;
                const float gt0 = acc[mi][ni][0] * DEQ, at0 = acc[mi][ni][1] * DEQ;
                const float gt1 = acc[mi][ni][2] * DEQ, at1 = acc[mi][ni][3] * DEQ;
                C[(size_t)row * oN + oc]       = f2f8(gt0 / (1.f + __expf(-gt0)) * at0);
                C[(size_t)(row + 8) * oN + oc] = f2f8(gt1 / (1.f + __expf(-gt1)) * at1);
            } else if constexpr (EPI == 2) {
                float* C = (float*)Cout;
                const float* resid = (const float*)aux1;
                const float* ls    = (const float*)aux2;
                const float2 lv = *(const float2*)(ls + col);
                const float2 x0 = *(const float2*)(resid + (size_t)row * N + col);
                const float2 x1 = *(const float2*)(resid + (size_t)(row + 8) * N + col);
                *(float2*)(C + (size_t)row * N + col) =
                    make_float2(x0.x + lv.x * acc[mi][ni][0] * DEQ,
                                x0.y + lv.y * acc[mi][ni][1] * DEQ);
                *(float2*)(C + (size_t)(row + 8) * N + col) =
                    make_float2(x1.x + lv.x * acc[mi][ni][2] * DEQ,
                                x1.y + lv.y * acc[mi][ni][3] * DEQ);
            } else {  // EPI == 3: qkv split
                if (col < 2048) {
                    uint8_t* dst = (uint8_t*)(col < 1024 ? Cout : (void*)aux1);
                    const int c = col & 1023;
                    *(uint16_t*)(dst + (size_t)row * 1024 + c) =
                        packf8(acc[mi][ni][0] * (DEQ * QS), acc[mi][ni][1] * (DEQ * QS));
                    *(uint16_t*)(dst + (size_t)(row + 8) * 1024 + c) =
                        packf8(acc[mi][ni][2] * (DEQ * QS), acc[mi][ni][3] * (DEQ * QS));
                } else {
                    __nv_bfloat16* v = (__nv_bfloat16*)aux2;
                    const int c = col - 2048;
                    *(uint32_t*)(v + (size_t)row * 1024 + c) =
                        packbf(acc[mi][ni][0] * DEQ, acc[mi][ni][1] * DEQ);
                    *(uint32_t*)(v + (size_t)(row + 8) * 1024 + c) =
                        packbf(acc[mi][ni][2] * DEQ, acc[mi][ni][3] * DEQ);
                }
            }
        }
    }
}

// ---------------- flash attention: diagonal-first tiles, fp8 QK^T ----------
#define AKV_STAGE 14336
#define ATTN_SMEM (10240 + 4 * AKV_STAGE)

__global__ void __launch_bounds__(256, 2) attn_tc(
        const uint8_t* __restrict__ q8, const uint8_t* __restrict__ k8,
        const __nv_bfloat16* __restrict__ vbf, uint8_t* __restrict__ outp) {
    extern __shared__ char smraw[];
    const uint32_t sQ = (uint32_t)__cvta_generic_to_shared(smraw);
    const int qt = (int)(gridDim.x - 1 - blockIdx.x);
    const int h = blockIdx.y, b = blockIdx.z;
    const int tid = threadIdx.x, lane = tid & 31, w = tid >> 5;
    const int g = lane >> 2, tg = lane & 3;
    const int lr = lane & 15, lh = lane >> 4;
    const float slope2 = exp2f(-0.5f * (float)(h + 1)) * LOG2E;
    const size_t rowbase = (size_t)b * SEQ;

    #pragma unroll
    for (int i = 0; i < 2; ++i) {
        const int c = tid + i * 256;
        const int row = c >> 2, off = (c & 3) * 16;
        cp16(sQ + row * 80 + off,
             q8 + (rowbase + qt * 128 + row) * 1024 + h * 64 + off);
    }
    CPCOMMIT();

    const int ktmax = 2 * qt + 1;
    auto issueKV = [&](int kt) {
        const uint32_t sK = sQ + 10240 + (kt & 3) * AKV_STAGE;
        const uint32_t sV = sK + 5120;
        {
            const int row = tid >> 2, off = (tid & 3) * 16;
            cp16(sK + row * 80 + off,
                 k8 + (rowbase + kt * 64 + row) * 1024 + h * 64 + off);
        }
        #pragma unroll
        for (int i = 0; i < 2; ++i) {
            const int c = tid + i * 256;
            const int row = c >> 3, off = (c & 7) * 8;
            cp16(sV + row * 144 + off * 2,
                 vbf + (rowbase + kt * 64 + row) * 1024 + h * 64 + off);
        }
        CPCOMMIT();
    };
    issueKV(ktmax);
    issueKV(ktmax - 1);
    if (ktmax >= 2) issueKV(ktmax - 2); else CPCOMMIT();

    asm volatile("cp.async.wait_group %0;\n" :: "n"(3));
    __syncthreads();
    uint32_t qa[2][4];
    #pragma unroll
    for (int ks = 0; ks < 2; ++ks)
        ldmx4(qa[ks], sQ + (w * 16 + lr) * 80 + ks * 32 + lh * 16);

    float o[8][4];
    #pragma unroll
    for (int ni = 0; ni < 8; ++ni)
        #pragma unroll
        for (int e = 0; e < 4; ++e) o[ni][e] = 0.f;
    float m0 = -1e30f, m1 = -1e30f, l0 = 0.f, l1 = 0.f;

    const int qr0 = qt * 128 + w * 16 + g;
    const int qwmin = qt * 128 + w * 16;
    const int qwmax = qwmin + 15;

    for (int kt = ktmax; kt >= 0; --kt) {
        asm volatile("cp.async.wait_group %0;\n" :: "n"(2));
        __syncthreads();
        if (kt * 64 <= qwmax) {
            const uint32_t sK = sQ + 10240 + (kt & 3) * AKV_STAGE;
            const uint32_t sV = sK + 5120;
            float sc[8][4];
            #pragma unroll
            for (int ni = 0; ni < 8; ++ni)
                #pragma unroll
                for (int e = 0; e < 4; ++e) sc[ni][e] = 0.f;
            #pragma unroll
            for (int ks = 0; ks < 2; ++ks) {
                uint32_t kb[4][4];
                #pragma unroll
                for (int nj = 0; nj < 4; ++nj)
                    ldmx4(kb[nj], sK + (nj * 16 + lr) * 80 + ks * 32 + lh * 16);
                #pragma unroll
                for (int ni = 0; ni < 8; ++ni)
                    MMA_FP8(sc[ni], qa[ks], kb[ni >> 1][ni & 1], kb[ni >> 1][(ni & 1) + 2]);
            }
            #pragma unroll
            for (int ni = 0; ni < 8; ++ni) {
                const float kcf = (float)(kt * 64 + ni * 8 + tg * 2);
                const float b0 = slope2 * kcf;
                const float b1 = slope2 * (kcf + 1.f);
                sc[ni][0] = sc[ni][0] * ATTN_SCL2 + b0;
                sc[ni][1] = sc[ni][1] * ATTN_SCL2 + b1;
                sc[ni][2] = sc[ni][2] * ATTN_SCL2 + b0;
                sc[ni][3] = sc[ni][3] * ATTN_SCL2 + b1;
            }
            if ((kt * 64 + 63) > qwmin) {
                #pragma unroll
                for (int ni = 0; ni < 8; ++ni) {
                    const int kc = kt * 64 + ni * 8 + tg * 2;
                    #pragma unroll
                    for (int e = 0; e < 4; ++e) {
                        const int q = (e < 2) ? qr0 : qr0 + 8;
                        if (kc + (e & 1) > q) sc[ni][e] = -1e30f;
                    }
                }
            }
            float rm0 = -1e30f, rm1 = -1e30f;
            #pragma unroll
            for (int ni = 0; ni < 8; ++ni) {
                rm0 = fmaxf(rm0, fmaxf(sc[ni][0], sc[ni][1]));
                rm1 = fmaxf(rm1, fmaxf(sc[ni][2], sc[ni][3]));
            }
            rm0 = fmaxf(rm0, __shfl_xor_sync(0xffffffffu, rm0, 1));
            rm0 = fmaxf(rm0, __shfl_xor_sync(0xffffffffu, rm0, 2));
            rm1 = fmaxf(rm1, __shfl_xor_sync(0xffffffffu, rm1, 1));
            rm1 = fmaxf(rm1, __shfl_xor_sync(0xffffffffu, rm1, 2));
            const float mn0 = fmaxf(m0, rm0), mn1 = fmaxf(m1, rm1);
            const bool stable = (mn0 == m0) && (mn1 == m1);
            if (!__all_sync(0xffffffffu, stable)) {
                const float cs0 = ex2(m0 - mn0), cs1 = ex2(m1 - mn1);
                l0 *= cs0; l1 *= cs1;
                m0 = mn0; m1 = mn1;
                #pragma unroll
                for (int ni = 0; ni < 8; ++ni) {
                    o[ni][0] *= cs0; o[ni][1] *= cs0;
                    o[ni][2] *= cs1; o[ni][3] *= cs1;
                }
            }
            float ps0 = 0.f, ps1 = 0.f;
            #pragma unroll
            for (int ni = 0; ni < 8; ++ni) {
                sc[ni][0] = ex2(sc[ni][0] - m0); ps0 += sc[ni][0];
                sc[ni][1] = ex2(sc[ni][1] - m0); ps0 += sc[ni][1];
                sc[ni][2] = ex2(sc[ni][2] - m1); ps1 += sc[ni][2];
                sc[ni][3] = ex2(sc[ni][3] - m1); ps1 += sc[ni][3];
            }
            ps0 += __shfl_xor_sync(0xffffffffu, ps0, 1);
            ps0 += __shfl_xor_sync(0xffffffffu, ps0, 2);
            ps1 += __shfl_xor_sync(0xffffffffu, ps1, 1);
            ps1 += __shfl_xor_sync(0xffffffffu, ps1, 2);
            l0 += ps0; l1 += ps1;
            #pragma unroll
            for (int j = 0; j < 4; ++j) {
                uint32_t pa[4];
                pa[0] = packbf(sc[2 * j][0],     sc[2 * j][1]);
                pa[1] = packbf(sc[2 * j][2],     sc[2 * j][3]);
                pa[2] = packbf(sc[2 * j + 1][0], sc[2 * j + 1][1]);
                pa[3] = packbf(sc[2 * j + 1][2], sc[2 * j + 1][3]);
                #pragma unroll
                for (int nt = 0; nt < 4; ++nt) {
                    uint32_t vb[4];
                    ldmx4t(vb, sV + ((j * 16 + (lane & 7) + ((lane >> 3) & 1) * 8) * 144)
                                  + (nt * 16 + ((lane >> 4) & 1) * 8) * 2);
                    MMA_BF16(o[2 * nt],     pa, vb[0], vb[1]);
                    MMA_BF16(o[2 * nt + 1], pa, vb[2], vb[3]);
                }
            }
        }
        if (kt - 3 >= 0) issueKV(kt - 3);
        else CPCOMMIT();
    }

    const float inv0 = 1.f / l0, inv1 = 1.f / l1;
    const size_t row0 = rowbase + qr0;
    #pragma unroll
    for (int ni = 0; ni < 8; ++ni) {
        const int col = h * 64 + ni * 8 + tg * 2;
        *(uint16_t*)(outp + row0 * D_MODEL + col) =
            packf8(o[ni][0] * inv0, o[ni][1] * inv0);
        *(uint16_t*)(outp + (row0 + 8) * D_MODEL + col) =
            packf8(o[ni][2] * inv1, o[ni][3] * inv1);
    }
}

// ---------------- launch ---------------------------------------------------
extern "C" void kernel_launch(void* const* d_in, const int* in_sizes, int n_in,
                              void* d_out, int out_size) {
    (void)in_sizes; (void)n_in; (void)out_size;
    const float* x    = (const float*)d_in[0];
    const float* ln1g = (const float*)d_in[2];
    const float* ln1b = (const float*)d_in[3];
    const float* Wqkv = (const float*)d_in[4];
    const float* Aqkv = (const float*)d_in[5];
    const float* Bqkv = (const float*)d_in[6];
    const float* Wo   = (const float*)d_in[7];
    const float* Ao   = (const float*)d_in[8];
    const float* Bo   = (const float*)d_in[9];
    const float* ln2g = (const float*)d_in[10];
    const float* ln2b = (const float*)d_in[11];
    const float* W1   = (const float*)d_in[12];
    const float* A1   = (const float*)d_in[13];
    const float* B1   = (const float*)d_in[14];
    const float* W2   = (const float*)d_in[15];
    const float* A2   = (const float*)d_in[16];
    const float* B2   = (const float*)d_in[17];
    const float* ls1  = (const float*)d_in[18];
    const float* ls2  = (const float*)d_in[19];
    float* out = (float*)d_out;

    uint8_t *p_xn, *p_attn, *p_ffin, *p_q8, *p_k8;
    uint8_t *p_weqkv, *p_weo, *p_we1, *p_we2;
    __nv_bfloat16 *p_v, *p_abf, *p_bt;
    float *p_x1;
    cudaGetSymbolAddress((void**)&p_xn,    g_xn8);
    cudaGetSymbolAddress((void**)&p_attn,  g_attn8);
    cudaGetSymbolAddress((void**)&p_ffin,  g_ffin8);
    cudaGetSymbolAddress((void**)&p_q8,    g_q8);
    cudaGetSymbolAddress((void**)&p_k8,    g_k8);
    cudaGetSymbolAddress((void**)&p_v,     g_v_bf);
    cudaGetSymbolAddress((void**)&p_x1,    g_x1);
    cudaGetSymbolAddress((void**)&p_weqkv, g_weqkv);
    cudaGetSymbolAddress((void**)&p_weo,   g_weo);
    cudaGetSymbolAddress((void**)&p_we1,   g_we1);
    cudaGetSymbolAddress((void**)&p_we2,   g_we2);
    cudaGetSymbolAddress((void**)&p_abf,   g_abf);
    cudaGetSymbolAddress((void**)&p_bt,    g_bt);

    const int smem_gemm = GSTG * GSTAGE_BYTES;   // 110592
    cudaFuncSetAttribute((const void*)gemm_fp8_nt<1>, cudaFuncAttributeMaxDynamicSharedMemorySize, smem_gemm);
    cudaFuncSetAttribute((const void*)gemm_fp8_nt<2>, cudaFuncAttributeMaxDynamicSharedMemorySize, smem_gemm);
    cudaFuncSetAttribute((const void*)gemm_fp8_nt<3>, cudaFuncAttributeMaxDynamicSharedMemorySize, smem_gemm);
    cudaFuncSetAttribute((const void*)attn_tc,        cudaFuncAttributeMaxDynamicSharedMemorySize, ATTN_SMEM);

    // 1: prep (A->bf16, B->B^T bf16)
    prep_kernel<<<2112, 256>>>(p_abf, p_bt, Aqkv, Ao, A1, A2, Bqkv, Bo, B1, B2);
    // 2: LN1
    ln_kernel<<<NTOK, 256>>>(x, ln1g, ln1b, p_xn);
    // 3: weff via tensor-core GEMM
    weff_gemm<<<1024, 256>>>(p_abf, p_bt, Wqkv, Wo, W1, W2,
                             p_weqkv, p_weo, p_we1, p_we2);
    // 4: qkv GEMM (profiled slot)
    gemm_fp8_nt<3><<<dim3(3072 / 128, NTOK / 128), 256, smem_gemm>>>(
        p_xn, p_weqkv, p_q8, p_k8, p_v, NTOK, 3072, 1024);
    // 5: attention
    attn_tc<<<dim3(SEQ / 128, NH, 2), 256, ATTN_SMEM>>>(p_q8, p_k8, p_v, p_attn);
    // 6: o-proj + residual
    gemm_fp8_nt<2><<<dim3(1024 / 128, NTOK / 128), 256, smem_gemm>>>(
        p_attn, p_weo, p_x1, x, ls1, NTOK, 1024, 1024);
    // 7: LN2
    ln_kernel<<<NTOK, 256>>>(p_x1, ln2g, ln2b, p_xn);
    // 8: W1 + swiglu
    gemm_fp8_nt<1><<<dim3(8192 / 128, NTOK / 128), 256, smem_gemm>>>(
        p_xn, p_we1, p_ffin, nullptr, nullptr, NTOK, 8192, 1024);
    // 9: W2 + residual -> out
    gemm_fp8_nt<2><<<dim3(1024 / 128, NTOK / 128), 256, smem_gemm>>>(
        p_ffin, p_we2, out, p_x1, ls2, NTOK, 1024, 4096);
}